// round 1
// baseline (speedup 1.0000x reference)
#include <cuda_runtime.h>

#define BB 16
#define DD 1024
#define QQ 128
#define HH 1024

// Scratch (device globals; no dynamic allocation allowed)
__device__ float g_S [BB * DD * QQ];   // logits S
__device__ float g_P1[BB * DD * QQ];   // softmax over q (S_d2q)
__device__ float g_P2[BB * DD * QQ];   // softmax over d (S_q2d)
__device__ float g_T [BB * QQ * HH];   // T[b,q,h] = sum_e P2[b,e,q] * U_d[b,e,h]
__device__ float g_sd[BB * DD];
__device__ float g_sq[BB * QQ];

// ---------------------------------------------------------------------------
// Row dot products: out[row] = sum_h X[row,h] * w[h]
// mode 0 -> g_sd, mode 1 -> g_sq. One warp per row.
// ---------------------------------------------------------------------------
__global__ void rowdot_kernel(const float* __restrict__ X,
                              const float* __restrict__ w,
                              int nrows, int mode) {
    int gw   = (blockIdx.x * blockDim.x + threadIdx.x) >> 5;
    int lane = threadIdx.x & 31;
    if (gw >= nrows) return;
    const float* row = X + (size_t)gw * HH;
    float s = 0.f;
    #pragma unroll
    for (int k = lane * 4; k < HH; k += 128) {
        float4 v  = *(const float4*)(row + k);
        float4 ww = *(const float4*)(w + k);
        s += v.x * ww.x + v.y * ww.y + v.z * ww.z + v.w * ww.w;
    }
    #pragma unroll
    for (int o = 16; o; o >>= 1) s += __shfl_xor_sync(0xffffffffu, s, o);
    if (lane == 0) {
        if (mode == 0) g_sd[gw] = s; else g_sq[gw] = s;
    }
}

// ---------------------------------------------------------------------------
// GEMM1 (NT, K=HH): S[b,d,q] = sum_h (Ud[b,d,h]*wdot[h]) * Uq[b,q,h]
//                             + sd[b,d] + sq[b,q] + bias
// Tiles: 128(m) x 128(n=full Q) x 8(k). 256 threads, 8x8 microtile.
// ---------------------------------------------------------------------------
__global__ __launch_bounds__(256) void gemm1_kernel(
    const float* __restrict__ Ud, const float* __restrict__ Uq,
    const float* __restrict__ wdot, const float* __restrict__ wcb) {
    __shared__ float As[8][128];
    __shared__ float Bs[8][128];
    int b  = blockIdx.z;
    int m0 = blockIdx.x * 128;
    const float* A  = Ud + (size_t)b * DD * HH;
    const float* Bq = Uq + (size_t)b * QQ * HH;
    int t  = threadIdx.x;
    int tx = t & 15, ty = t >> 4;
    int lr = t >> 1, lk = (t & 1) * 4;

    float acc[8][8];
    #pragma unroll
    for (int i = 0; i < 8; i++)
        #pragma unroll
        for (int j = 0; j < 8; j++) acc[i][j] = 0.f;

    for (int k0 = 0; k0 < HH; k0 += 8) {
        float4 a4 = *(const float4*)(A + (size_t)(m0 + lr) * HH + k0 + lk);
        float4 w4 = *(const float4*)(wdot + k0 + lk);
        float4 b4 = *(const float4*)(Bq + (size_t)lr * HH + k0 + lk);
        a4.x *= w4.x; a4.y *= w4.y; a4.z *= w4.z; a4.w *= w4.w;
        __syncthreads();
        As[lk + 0][lr] = a4.x; As[lk + 1][lr] = a4.y;
        As[lk + 2][lr] = a4.z; As[lk + 3][lr] = a4.w;
        Bs[lk + 0][lr] = b4.x; Bs[lk + 1][lr] = b4.y;
        Bs[lk + 2][lr] = b4.z; Bs[lk + 3][lr] = b4.w;
        __syncthreads();
        #pragma unroll
        for (int kk = 0; kk < 8; kk++) {
            float ar[8], br[8];
            #pragma unroll
            for (int i = 0; i < 8; i++) ar[i] = As[kk][ty * 8 + i];
            #pragma unroll
            for (int j = 0; j < 8; j++) br[j] = Bs[kk][tx * 8 + j];
            #pragma unroll
            for (int i = 0; i < 8; i++)
                #pragma unroll
                for (int j = 0; j < 8; j++)
                    acc[i][j] = fmaf(ar[i], br[j], acc[i][j]);
        }
    }

    float bias = wcb[0];
    float sqv[8];
    #pragma unroll
    for (int j = 0; j < 8; j++) sqv[j] = g_sq[b * QQ + tx * 8 + j];

    #pragma unroll
    for (int i = 0; i < 8; i++) {
        int m = m0 + ty * 8 + i;
        float sdv = g_sd[b * DD + m] + bias;
        float* dst = g_S + ((size_t)b * DD + m) * QQ + tx * 8;
        float4 o0, o1;
        o0.x = acc[i][0] + sdv + sqv[0]; o0.y = acc[i][1] + sdv + sqv[1];
        o0.z = acc[i][2] + sdv + sqv[2]; o0.w = acc[i][3] + sdv + sqv[3];
        o1.x = acc[i][4] + sdv + sqv[4]; o1.y = acc[i][5] + sdv + sqv[5];
        o1.z = acc[i][6] + sdv + sqv[6]; o1.w = acc[i][7] + sdv + sqv[7];
        *(float4*)dst = o0;
        *(float4*)(dst + 4) = o1;
    }
}

// ---------------------------------------------------------------------------
// Softmax over q (axis -1). One warp per (b,d) row of length 128.
// ---------------------------------------------------------------------------
__global__ void softmax_d2q_kernel(const int* __restrict__ qm,
                                   const int* __restrict__ dmk) {
    int row = (blockIdx.x * blockDim.x + threadIdx.x) >> 5;
    if (row >= BB * DD) return;
    int lane = threadIdx.x & 31;
    int b = row >> 10;  // DD = 1024
    int dmv = dmk[row];
    const float* src = g_S + (size_t)row * QQ;
    float4 v = *(const float4*)(src + lane * 4);
    int4 q4 = *(const int4*)(qm + b * QQ + lane * 4);
    int mk0 = (dmv > 0) && (q4.x > 0);
    int mk1 = (dmv > 0) && (q4.y > 0);
    int mk2 = (dmv > 0) && (q4.z > 0);
    int mk3 = (dmv > 0) && (q4.w > 0);
    float l0 = mk0 ? v.x : -1e30f;
    float l1 = mk1 ? v.y : -1e30f;
    float l2 = mk2 ? v.z : -1e30f;
    float l3 = mk3 ? v.w : -1e30f;
    float mx = fmaxf(fmaxf(l0, l1), fmaxf(l2, l3));
    #pragma unroll
    for (int o = 16; o; o >>= 1) mx = fmaxf(mx, __shfl_xor_sync(0xffffffffu, mx, o));
    float e0 = __expf(l0 - mx), e1 = __expf(l1 - mx);
    float e2 = __expf(l2 - mx), e3 = __expf(l3 - mx);
    float s = e0 + e1 + e2 + e3;
    #pragma unroll
    for (int o = 16; o; o >>= 1) s += __shfl_xor_sync(0xffffffffu, s, o);
    float inv = 1.f / s;
    float4 ov;
    ov.x = mk0 ? e0 * inv : 0.f;
    ov.y = mk1 ? e1 * inv : 0.f;
    ov.z = mk2 ? e2 * inv : 0.f;
    ov.w = mk3 ? e3 * inv : 0.f;
    *(float4*)(g_P1 + (size_t)row * QQ + lane * 4) = ov;
}

// ---------------------------------------------------------------------------
// Softmax over d (axis -2). Block (32,8): 32 coalesced q-columns, 8 threads
// cooperate down the d dimension. Online max/sum, merge across ty via smem.
// ---------------------------------------------------------------------------
__global__ void softmax_q2d_kernel(const int* __restrict__ qm,
                                   const int* __restrict__ dmk) {
    __shared__ float sm[8][32], ss[8][32];
    int b  = blockIdx.y;
    int tx = threadIdx.x, ty = threadIdx.y;
    int q  = blockIdx.x * 32 + tx;
    int qmv = qm[b * QQ + q];
    const float* base = g_S + (size_t)b * DD * QQ + q;
    float m = -1e30f, s = 0.f;
    for (int d = ty; d < DD; d += 8) {
        int mk = (qmv > 0) && (dmk[b * DD + d] > 0);
        float v = mk ? base[(size_t)d * QQ] : -1e30f;
        float nm = fmaxf(m, v);
        s = s * __expf(m - nm) + __expf(v - nm);
        m = nm;
    }
    sm[ty][tx] = m; ss[ty][tx] = s;
    __syncthreads();
    float M = -1e30f;
    #pragma unroll
    for (int j = 0; j < 8; j++) M = fmaxf(M, sm[j][tx]);
    float Ssum = 0.f;
    #pragma unroll
    for (int j = 0; j < 8; j++) Ssum += ss[j][tx] * __expf(sm[j][tx] - M);
    float inv = 1.f / Ssum;
    float* dst = g_P2 + (size_t)b * DD * QQ + q;
    for (int d = ty; d < DD; d += 8) {
        int mk = (qmv > 0) && (dmk[b * DD + d] > 0);
        float v = base[(size_t)d * QQ];
        dst[(size_t)d * QQ] = mk ? __expf(v - M) * inv : 0.f;
    }
}

// ---------------------------------------------------------------------------
// GEMM3 (TN, K=DD): T[b,q,h] = sum_d P2[b,d,q] * Ud[b,d,h]
// A[k][m] = P2 (m contiguous), B[k][n] = Ud (n contiguous). M = 128 = Q.
// ---------------------------------------------------------------------------
__global__ __launch_bounds__(256) void gemm3_kernel(const float* __restrict__ Ud) {
    __shared__ float As[8][128];
    __shared__ float Bs[8][128];
    int b  = blockIdx.z;
    int n0 = blockIdx.x * 128;
    const float* A  = g_P2 + (size_t)b * DD * QQ;
    const float* Bm = Ud + (size_t)b * DD * HH;
    int t  = threadIdx.x;
    int tx = t & 15, ty = t >> 4;
    int kr = t >> 5, cb = (t & 31) * 4;

    float acc[8][8];
    #pragma unroll
    for (int i = 0; i < 8; i++)
        #pragma unroll
        for (int j = 0; j < 8; j++) acc[i][j] = 0.f;

    for (int k0 = 0; k0 < DD; k0 += 8) {
        float4 a4 = *(const float4*)(A + (size_t)(k0 + kr) * QQ + cb);
        float4 b4 = *(const float4*)(Bm + (size_t)(k0 + kr) * HH + n0 + cb);
        __syncthreads();
        *(float4*)&As[kr][cb] = a4;
        *(float4*)&Bs[kr][cb] = b4;
        __syncthreads();
        #pragma unroll
        for (int kk = 0; kk < 8; kk++) {
            float ar[8], br[8];
            #pragma unroll
            for (int i = 0; i < 8; i++) ar[i] = As[kk][ty * 8 + i];
            #pragma unroll
            for (int j = 0; j < 8; j++) br[j] = Bs[kk][tx * 8 + j];
            #pragma unroll
            for (int i = 0; i < 8; i++)
                #pragma unroll
                for (int j = 0; j < 8; j++)
                    acc[i][j] = fmaf(ar[i], br[j], acc[i][j]);
        }
    }
    #pragma unroll
    for (int i = 0; i < 8; i++) {
        int m = ty * 8 + i;
        float* dst = g_T + ((size_t)b * QQ + m) * HH + n0 + tx * 8;
        float4 o0 = make_float4(acc[i][0], acc[i][1], acc[i][2], acc[i][3]);
        float4 o1 = make_float4(acc[i][4], acc[i][5], acc[i][6], acc[i][7]);
        *(float4*)dst = o0;
        *(float4*)(dst + 4) = o1;
    }
}

// ---------------------------------------------------------------------------
// GEMM NN (K=QQ=128): C[b,m,n] = sum_q P1[b,m,q] * Bm[b,q,n]
// mode 0: Bm = Uq; epilogue writes out slice0 = Ud, slice1 = C, slice2 = Ud*C
// mode 1: Bm = g_T; epilogue writes out slice3 = Ud*C
// out row stride is 4*HH.
// ---------------------------------------------------------------------------
__global__ __launch_bounds__(256) void gemm_nn_kernel(
    const float* __restrict__ Uq, const float* __restrict__ Ud,
    float* __restrict__ out, int mode) {
    __shared__ float As[8][128];
    __shared__ float Bs[8][128];
    int b  = blockIdx.z;
    int n0 = blockIdx.x * 128;
    int m0 = blockIdx.y * 128;
    const float* A  = g_P1 + (size_t)b * DD * QQ;
    const float* Bm = (mode == 0) ? (Uq + (size_t)b * QQ * HH)
                                  : (g_T + (size_t)b * QQ * HH);
    int t  = threadIdx.x;
    int tx = t & 15, ty = t >> 4;
    int alr = t >> 1, alk = (t & 1) * 4;
    int bkr = t >> 5, bnb = (t & 31) * 4;

    float acc[8][8];
    #pragma unroll
    for (int i = 0; i < 8; i++)
        #pragma unroll
        for (int j = 0; j < 8; j++) acc[i][j] = 0.f;

    for (int k0 = 0; k0 < QQ; k0 += 8) {
        float4 a4 = *(const float4*)(A + (size_t)(m0 + alr) * QQ + k0 + alk);
        float4 b4 = *(const float4*)(Bm + (size_t)(k0 + bkr) * HH + n0 + bnb);
        __syncthreads();
        As[alk + 0][alr] = a4.x; As[alk + 1][alr] = a4.y;
        As[alk + 2][alr] = a4.z; As[alk + 3][alr] = a4.w;
        *(float4*)&Bs[bkr][bnb] = b4;
        __syncthreads();
        #pragma unroll
        for (int kk = 0; kk < 8; kk++) {
            float ar[8], br[8];
            #pragma unroll
            for (int i = 0; i < 8; i++) ar[i] = As[kk][ty * 8 + i];
            #pragma unroll
            for (int j = 0; j < 8; j++) br[j] = Bs[kk][tx * 8 + j];
            #pragma unroll
            for (int i = 0; i < 8; i++)
                #pragma unroll
                for (int j = 0; j < 8; j++)
                    acc[i][j] = fmaf(ar[i], br[j], acc[i][j]);
        }
    }

    #pragma unroll
    for (int i = 0; i < 8; i++) {
        int m = m0 + ty * 8 + i;
        size_t urow = ((size_t)b * DD + m) * HH + n0 + tx * 8;
        float4 u0 = *(const float4*)(Ud + urow);
        float4 u1 = *(const float4*)(Ud + urow + 4);
        size_t orow = ((size_t)b * DD + m) * (4 * HH) + n0 + tx * 8;
        float4 a0 = make_float4(acc[i][0], acc[i][1], acc[i][2], acc[i][3]);
        float4 a1 = make_float4(acc[i][4], acc[i][5], acc[i][6], acc[i][7]);
        float4 p0 = make_float4(u0.x * a0.x, u0.y * a0.y, u0.z * a0.z, u0.w * a0.w);
        float4 p1 = make_float4(u1.x * a1.x, u1.y * a1.y, u1.z * a1.z, u1.w * a1.w);
        if (mode == 0) {
            *(float4*)(out + orow)          = u0;
            *(float4*)(out + orow + 4)      = u1;
            *(float4*)(out + orow + HH)     = a0;
            *(float4*)(out + orow + HH + 4) = a1;
            *(float4*)(out + orow + 2 * HH)     = p0;
            *(float4*)(out + orow + 2 * HH + 4) = p1;
        } else {
            *(float4*)(out + orow + 3 * HH)     = p0;
            *(float4*)(out + orow + 3 * HH + 4) = p1;
        }
    }
}

// ---------------------------------------------------------------------------
extern "C" void kernel_launch(void* const* d_in, const int* in_sizes, int n_in,
                              void* d_out, int out_size) {
    const float* Ud  = (const float*)d_in[0];
    const float* Uq  = (const float*)d_in[1];
    const float* wcw = (const float*)d_in[2];
    const float* wcb = (const float*)d_in[3];
    const int*   qm  = (const int*)d_in[4];
    const int*   dmk = (const int*)d_in[5];
    float* out = (float*)d_out;

    // s_d = Ud @ w_d, s_q = Uq @ w_q
    rowdot_kernel<<<(BB * DD) / 8, 256>>>(Ud, wcw, BB * DD, 0);
    rowdot_kernel<<<(BB * QQ) / 8, 256>>>(Uq, wcw + HH, BB * QQ, 1);

    // S = (Ud * w_dot) @ Uq^T + s_d + s_q + bias
    gemm1_kernel<<<dim3(8, 1, BB), 256>>>(Ud, Uq, wcw + 2 * HH, wcb);

    // softmaxes
    softmax_d2q_kernel<<<(BB * DD) / 8, 256>>>(qm, dmk);
    softmax_q2d_kernel<<<dim3(QQ / 32, BB), dim3(32, 8)>>>(qm, dmk);

    // T = P2^T @ Ud   (K = D)
    gemm3_kernel<<<dim3(HH / 128, 1, BB), 256>>>(Ud);

    // A_d2q = P1 @ Uq  -> out slices 0,1,2
    gemm_nn_kernel<<<dim3(HH / 128, DD / 128, BB), 256>>>(Uq, Ud, out, 0);
    // A_q2d = P1 @ T   -> out slice 3
    gemm_nn_kernel<<<dim3(HH / 128, DD / 128, BB), 256>>>(Uq, Ud, out, 1);
}

// round 3
// speedup vs baseline: 1.0049x; 1.0049x over previous
#include <cuda_runtime.h>
#include <cstdint>

#define BB 16
#define DD 1024
#define QQ 128
#define HH 1024

// Scratch (device globals; no dynamic allocation allowed)
__device__ float g_S [BB * DD * QQ];   // logits S
__device__ float g_P1[BB * DD * QQ];   // softmax over q (S_d2q)
__device__ float g_P2[BB * DD * QQ];   // softmax over d (S_q2d)
__device__ float g_T [BB * QQ * HH];   // T[b,q,h] = sum_e P2[b,e,q] * U_d[b,e,h]
__device__ float g_sd[BB * DD];
__device__ float g_sq[BB * QQ];

// ---------------- packed f32x2 helpers (Blackwell family, not "a"-gated) ----
typedef unsigned long long u64t;
__device__ __forceinline__ u64t pack2(float x, float y) {
    u64t r;
    asm("mov.b64 %0, {%1, %2};" : "=l"(r) : "f"(x), "f"(y));
    return r;
}
__device__ __forceinline__ void unpack2(u64t v, float& x, float& y) {
    asm("mov.b64 {%0, %1}, %2;" : "=f"(x), "=f"(y) : "l"(v));
}
__device__ __forceinline__ void fma2(u64t& d, u64t a, u64t b) {
    asm("fma.rn.f32x2 %0, %1, %2, %0;" : "+l"(d) : "l"(a), "l"(b));
}

// Shared 8x8 microtile compute step on packed pairs.
// acc2[i][j] holds columns (2j, 2j+1) of row i.
#define MICROTILE_STEP(As, Bs)                                               \
    do {                                                                     \
        _Pragma("unroll")                                                    \
        for (int kk = 0; kk < 8; kk++) {                                     \
            float ar[8];                                                     \
            u64t br2[4];                                                     \
            _Pragma("unroll")                                                \
            for (int i = 0; i < 8; i++) ar[i] = As[kk][ty * 8 + i];          \
            _Pragma("unroll")                                                \
            for (int j = 0; j < 4; j++) {                                    \
                float2 bp = *(const float2*)&Bs[kk][tx * 8 + 2 * j];         \
                br2[j] = pack2(bp.x, bp.y);                                  \
            }                                                                \
            _Pragma("unroll")                                                \
            for (int i = 0; i < 8; i++) {                                    \
                u64t ar2 = pack2(ar[i], ar[i]);                              \
                _Pragma("unroll")                                            \
                for (int j = 0; j < 4; j++) fma2(acc2[i][j], ar2, br2[j]);   \
            }                                                                \
        }                                                                    \
    } while (0)

// ---------------------------------------------------------------------------
// Row dot products: out[row] = sum_h X[row,h] * w[h]
// ---------------------------------------------------------------------------
__global__ void rowdot_kernel(const float* __restrict__ X,
                              const float* __restrict__ w,
                              int nrows, int mode) {
    int gw   = (blockIdx.x * blockDim.x + threadIdx.x) >> 5;
    int lane = threadIdx.x & 31;
    if (gw >= nrows) return;
    const float* row = X + (size_t)gw * HH;
    float s = 0.f;
    #pragma unroll
    for (int k = lane * 4; k < HH; k += 128) {
        float4 v  = *(const float4*)(row + k);
        float4 ww = *(const float4*)(w + k);
        s += v.x * ww.x + v.y * ww.y + v.z * ww.z + v.w * ww.w;
    }
    #pragma unroll
    for (int o = 16; o; o >>= 1) s += __shfl_xor_sync(0xffffffffu, s, o);
    if (lane == 0) {
        if (mode == 0) g_sd[gw] = s; else g_sq[gw] = s;
    }
}

// ---------------------------------------------------------------------------
// GEMM1 (NT, K=HH): S[b,d,q] = sum_h (Ud[b,d,h]*wdot[h]) * Uq[b,q,h]
//                             + sd[b,d] + sq[b,q] + bias
// ---------------------------------------------------------------------------
__global__ __launch_bounds__(256, 2) void gemm1_kernel(
    const float* __restrict__ Ud, const float* __restrict__ Uq,
    const float* __restrict__ wdot, const float* __restrict__ wcb) {
    __shared__ float As[8][128];
    __shared__ float Bs[8][128];
    int b  = blockIdx.z;
    int m0 = blockIdx.x * 128;
    const float* A  = Ud + (size_t)b * DD * HH;
    const float* Bq = Uq + (size_t)b * QQ * HH;
    int t  = threadIdx.x;
    int tx = t & 15, ty = t >> 4;
    int lr = t >> 1, lk = (t & 1) * 4;

    u64t acc2[8][4];
    #pragma unroll
    for (int i = 0; i < 8; i++)
        #pragma unroll
        for (int j = 0; j < 4; j++) acc2[i][j] = 0ull;

    for (int k0 = 0; k0 < HH; k0 += 8) {
        float4 a4 = *(const float4*)(A + (size_t)(m0 + lr) * HH + k0 + lk);
        float4 w4 = *(const float4*)(wdot + k0 + lk);
        float4 b4 = *(const float4*)(Bq + (size_t)lr * HH + k0 + lk);
        a4.x *= w4.x; a4.y *= w4.y; a4.z *= w4.z; a4.w *= w4.w;
        __syncthreads();
        As[lk + 0][lr] = a4.x; As[lk + 1][lr] = a4.y;
        As[lk + 2][lr] = a4.z; As[lk + 3][lr] = a4.w;
        Bs[lk + 0][lr] = b4.x; Bs[lk + 1][lr] = b4.y;
        Bs[lk + 2][lr] = b4.z; Bs[lk + 3][lr] = b4.w;
        __syncthreads();
        MICROTILE_STEP(As, Bs);
    }

    float bias = wcb[0];
    float sqv[8];
    #pragma unroll
    for (int j = 0; j < 8; j++) sqv[j] = g_sq[b * QQ + tx * 8 + j];

    #pragma unroll
    for (int i = 0; i < 8; i++) {
        int m = m0 + ty * 8 + i;
        float sdv = g_sd[b * DD + m] + bias;
        float a[8];
        #pragma unroll
        for (int j = 0; j < 4; j++) unpack2(acc2[i][j], a[2 * j], a[2 * j + 1]);
        float* dst = g_S + ((size_t)b * DD + m) * QQ + tx * 8;
        float4 o0, o1;
        o0.x = a[0] + sdv + sqv[0]; o0.y = a[1] + sdv + sqv[1];
        o0.z = a[2] + sdv + sqv[2]; o0.w = a[3] + sdv + sqv[3];
        o1.x = a[4] + sdv + sqv[4]; o1.y = a[5] + sdv + sqv[5];
        o1.z = a[6] + sdv + sqv[6]; o1.w = a[7] + sdv + sqv[7];
        *(float4*)dst = o0;
        *(float4*)(dst + 4) = o1;
    }
}

// ---------------------------------------------------------------------------
// Softmax over q (axis -1). One warp per (b,d) row of length 128.
// ---------------------------------------------------------------------------
__global__ void softmax_d2q_kernel(const int* __restrict__ qm,
                                   const int* __restrict__ dmk) {
    int row = (blockIdx.x * blockDim.x + threadIdx.x) >> 5;
    if (row >= BB * DD) return;
    int lane = threadIdx.x & 31;
    int b = row >> 10;
    int dmv = dmk[row];
    const float* src = g_S + (size_t)row * QQ;
    float4 v = *(const float4*)(src + lane * 4);
    int4 q4 = *(const int4*)(qm + b * QQ + lane * 4);
    int mk0 = (dmv > 0) && (q4.x > 0);
    int mk1 = (dmv > 0) && (q4.y > 0);
    int mk2 = (dmv > 0) && (q4.z > 0);
    int mk3 = (dmv > 0) && (q4.w > 0);
    float l0 = mk0 ? v.x : -1e30f;
    float l1 = mk1 ? v.y : -1e30f;
    float l2 = mk2 ? v.z : -1e30f;
    float l3 = mk3 ? v.w : -1e30f;
    float mx = fmaxf(fmaxf(l0, l1), fmaxf(l2, l3));
    #pragma unroll
    for (int o = 16; o; o >>= 1) mx = fmaxf(mx, __shfl_xor_sync(0xffffffffu, mx, o));
    float e0 = __expf(l0 - mx), e1 = __expf(l1 - mx);
    float e2 = __expf(l2 - mx), e3 = __expf(l3 - mx);
    float s = e0 + e1 + e2 + e3;
    #pragma unroll
    for (int o = 16; o; o >>= 1) s += __shfl_xor_sync(0xffffffffu, s, o);
    float inv = 1.f / s;
    float4 ov;
    ov.x = mk0 ? e0 * inv : 0.f;
    ov.y = mk1 ? e1 * inv : 0.f;
    ov.z = mk2 ? e2 * inv : 0.f;
    ov.w = mk3 ? e3 * inv : 0.f;
    *(float4*)(g_P1 + (size_t)row * QQ + lane * 4) = ov;
}

// ---------------------------------------------------------------------------
// Softmax over d (axis -2). Block (32,8).
// ---------------------------------------------------------------------------
__global__ void softmax_q2d_kernel(const int* __restrict__ qm,
                                   const int* __restrict__ dmk) {
    __shared__ float sm[8][32], ss[8][32];
    int b  = blockIdx.y;
    int tx = threadIdx.x, ty = threadIdx.y;
    int q  = blockIdx.x * 32 + tx;
    int qmv = qm[b * QQ + q];
    const float* base = g_S + (size_t)b * DD * QQ + q;
    float m = -1e30f, s = 0.f;
    for (int d = ty; d < DD; d += 8) {
        int mk = (qmv > 0) && (dmk[b * DD + d] > 0);
        float v = mk ? base[(size_t)d * QQ] : -1e30f;
        float nm = fmaxf(m, v);
        s = s * __expf(m - nm) + __expf(v - nm);
        m = nm;
    }
    sm[ty][tx] = m; ss[ty][tx] = s;
    __syncthreads();
    float M = -1e30f;
    #pragma unroll
    for (int j = 0; j < 8; j++) M = fmaxf(M, sm[j][tx]);
    float Ssum = 0.f;
    #pragma unroll
    for (int j = 0; j < 8; j++) Ssum += ss[j][tx] * __expf(sm[j][tx] - M);
    float inv = 1.f / Ssum;
    float* dst = g_P2 + (size_t)b * DD * QQ + q;
    for (int d = ty; d < DD; d += 8) {
        int mk = (qmv > 0) && (dmk[b * DD + d] > 0);
        float v = base[(size_t)d * QQ];
        dst[(size_t)d * QQ] = mk ? __expf(v - M) * inv : 0.f;
    }
}

// ---------------------------------------------------------------------------
// GEMM3 (TN, K=DD): T[b,q,h] = sum_d P2[b,d,q] * Ud[b,d,h]
// ---------------------------------------------------------------------------
__global__ __launch_bounds__(256, 2) void gemm3_kernel(const float* __restrict__ Ud) {
    __shared__ float As[8][128];
    __shared__ float Bs[8][128];
    int b  = blockIdx.z;
    int n0 = blockIdx.x * 128;
    const float* A  = g_P2 + (size_t)b * DD * QQ;
    const float* Bm = Ud + (size_t)b * DD * HH;
    int t  = threadIdx.x;
    int tx = t & 15, ty = t >> 4;
    int kr = t >> 5, cb = (t & 31) * 4;

    u64t acc2[8][4];
    #pragma unroll
    for (int i = 0; i < 8; i++)
        #pragma unroll
        for (int j = 0; j < 4; j++) acc2[i][j] = 0ull;

    for (int k0 = 0; k0 < DD; k0 += 8) {
        float4 a4 = *(const float4*)(A + (size_t)(k0 + kr) * QQ + cb);
        float4 b4 = *(const float4*)(Bm + (size_t)(k0 + kr) * HH + n0 + cb);
        __syncthreads();
        *(float4*)&As[kr][cb] = a4;
        *(float4*)&Bs[kr][cb] = b4;
        __syncthreads();
        MICROTILE_STEP(As, Bs);
    }
    #pragma unroll
    for (int i = 0; i < 8; i++) {
        int m = ty * 8 + i;
        float a[8];
        #pragma unroll
        for (int j = 0; j < 4; j++) unpack2(acc2[i][j], a[2 * j], a[2 * j + 1]);
        float* dst = g_T + ((size_t)b * QQ + m) * HH + n0 + tx * 8;
        *(float4*)dst       = make_float4(a[0], a[1], a[2], a[3]);
        *(float4*)(dst + 4) = make_float4(a[4], a[5], a[6], a[7]);
    }
}

// ---------------------------------------------------------------------------
// GEMM NN (K=QQ=128): C[b,m,n] = sum_q P1[b,m,q] * Bm[b,q,n]
// mode 0: Bm = Uq; writes slices 0,1,2.  mode 1: Bm = g_T; writes slice 3.
// ---------------------------------------------------------------------------
__global__ __launch_bounds__(256, 2) void gemm_nn_kernel(
    const float* __restrict__ Uq, const float* __restrict__ Ud,
    float* __restrict__ out, int mode) {
    __shared__ float As[8][128];
    __shared__ float Bs[8][128];
    int b  = blockIdx.z;
    int n0 = blockIdx.x * 128;
    int m0 = blockIdx.y * 128;
    const float* A  = g_P1 + (size_t)b * DD * QQ;
    const float* Bm = (mode == 0) ? (Uq + (size_t)b * QQ * HH)
                                  : (g_T + (size_t)b * QQ * HH);
    int t  = threadIdx.x;
    int tx = t & 15, ty = t >> 4;
    int alr = t >> 1, alk = (t & 1) * 4;
    int bkr = t >> 5, bnb = (t & 31) * 4;

    u64t acc2[8][4];
    #pragma unroll
    for (int i = 0; i < 8; i++)
        #pragma unroll
        for (int j = 0; j < 4; j++) acc2[i][j] = 0ull;

    for (int k0 = 0; k0 < QQ; k0 += 8) {
        float4 a4 = *(const float4*)(A + (size_t)(m0 + alr) * QQ + k0 + alk);
        float4 b4 = *(const float4*)(Bm + (size_t)(k0 + bkr) * HH + n0 + bnb);
        __syncthreads();
        As[alk + 0][alr] = a4.x; As[alk + 1][alr] = a4.y;
        As[alk + 2][alr] = a4.z; As[alk + 3][alr] = a4.w;
        *(float4*)&Bs[bkr][bnb] = b4;
        __syncthreads();
        MICROTILE_STEP(As, Bs);
    }

    #pragma unroll
    for (int i = 0; i < 8; i++) {
        int m = m0 + ty * 8 + i;
        float a[8];
        #pragma unroll
        for (int j = 0; j < 4; j++) unpack2(acc2[i][j], a[2 * j], a[2 * j + 1]);
        size_t urow = ((size_t)b * DD + m) * HH + n0 + tx * 8;
        float4 u0 = *(const float4*)(Ud + urow);
        float4 u1 = *(const float4*)(Ud + urow + 4);
        size_t orow = ((size_t)b * DD + m) * (4 * HH) + n0 + tx * 8;
        float4 a0 = make_float4(a[0], a[1], a[2], a[3]);
        float4 a1 = make_float4(a[4], a[5], a[6], a[7]);
        float4 p0 = make_float4(u0.x * a0.x, u0.y * a0.y, u0.z * a0.z, u0.w * a0.w);
        float4 p1 = make_float4(u1.x * a1.x, u1.y * a1.y, u1.z * a1.z, u1.w * a1.w);
        if (mode == 0) {
            *(float4*)(out + orow)          = u0;
            *(float4*)(out + orow + 4)      = u1;
            *(float4*)(out + orow + HH)     = a0;
            *(float4*)(out + orow + HH + 4) = a1;
            *(float4*)(out + orow + 2 * HH)     = p0;
            *(float4*)(out + orow + 2 * HH + 4) = p1;
        } else {
            *(float4*)(out + orow + 3 * HH)     = p0;
            *(float4*)(out + orow + 3 * HH + 4) = p1;
        }
    }
}

// ---------------------------------------------------------------------------
extern "C" void kernel_launch(void* const* d_in, const int* in_sizes, int n_in,
                              void* d_out, int out_size) {
    const float* Ud  = (const float*)d_in[0];
    const float* Uq  = (const float*)d_in[1];
    const float* wcw = (const float*)d_in[2];
    const float* wcb = (const float*)d_in[3];
    const int*   qm  = (const int*)d_in[4];
    const int*   dmk = (const int*)d_in[5];
    float* out = (float*)d_out;

    rowdot_kernel<<<(BB * DD) / 8, 256>>>(Ud, wcw, BB * DD, 0);
    rowdot_kernel<<<(BB * QQ) / 8, 256>>>(Uq, wcw + HH, BB * QQ, 1);

    gemm1_kernel<<<dim3(8, 1, BB), 256>>>(Ud, Uq, wcw + 2 * HH, wcb);

    softmax_d2q_kernel<<<(BB * DD) / 8, 256>>>(qm, dmk);
    softmax_q2d_kernel<<<dim3(QQ / 32, BB), dim3(32, 8)>>>(qm, dmk);

    gemm3_kernel<<<dim3(HH / 128, 1, BB), 256>>>(Ud);

    gemm_nn_kernel<<<dim3(HH / 128, DD / 128, BB), 256>>>(Uq, Ud, out, 0);
    gemm_nn_kernel<<<dim3(HH / 128, DD / 128, BB), 256>>>(Uq, Ud, out, 1);
}

// round 4
// speedup vs baseline: 1.5676x; 1.5599x over previous
#include <cuda_runtime.h>
#include <cuda_bf16.h>
#include <cstdint>

#define BB 16
#define DD 1024
#define QQ 128
#define HH 1024

// ---------------- scratch (device globals) ----------------------------------
__device__ float g_S  [BB * DD * QQ];   // logits
__device__ float g_P1 [BB * DD * QQ];   // softmax over q (S_d2q) [b,d,q]
__device__ float g_P2t[BB * QQ * DD];   // softmax over d (S_q2d) transposed [b,q,d]
__device__ float g_Tt [BB * HH * QQ];   // Tt[b,h,q] = sum_d P2[b,d,q]*Ud[b,d,h]
__device__ float g_Udt[BB * HH * DD];   // Ud^T [b,h,d]
__device__ float g_Uqt[BB * HH * QQ];   // Uq^T [b,h,q]
__device__ float g_sd [BB * DD];
__device__ float g_sq [BB * QQ];

// ---------------- mma helpers ------------------------------------------------
#define SROW 40   // smem row stride in bf16 elements (80 B, conflict-free)

__device__ __forceinline__ uint32_t L32(const __nv_bfloat16* p) {
    return *(const uint32_t*)p;
}
__device__ __forceinline__ void mma_bf16(float* c, const uint32_t* a, const uint32_t* b) {
    asm volatile(
        "mma.sync.aligned.m16n8k16.row.col.f32.bf16.bf16.f32 "
        "{%0,%1,%2,%3}, {%4,%5,%6,%7}, {%8,%9}, {%0,%1,%2,%3};"
        : "+f"(c[0]), "+f"(c[1]), "+f"(c[2]), "+f"(c[3])
        : "r"(a[0]), "r"(a[1]), "r"(a[2]), "r"(a[3]), "r"(b[0]), "r"(b[1]));
}
__device__ __forceinline__ void bsplit(float x, __nv_bfloat16& h, __nv_bfloat16& l) {
    h = __float2bfloat16(x);
    l = __float2bfloat16(x - __bfloat162float(h));
}
// stage a 128x32 fp32 tile (row-major, leading dim ld) into hi/lo bf16 smem
__device__ __forceinline__ void stage_tile(const float* __restrict__ src, int ld, int k0,
                                           __nv_bfloat16* sh, __nv_bfloat16* sl, int t) {
    #pragma unroll
    for (int v = 0; v < 4; v++) {
        int idx = v * 256 + t;
        int row = idx >> 3;
        int cs  = (idx & 7) * 4;
        float4 x = *(const float4*)(src + (size_t)row * ld + k0 + cs);
        __nv_bfloat16 h0, l0, h1, l1, h2, l2, h3, l3;
        bsplit(x.x, h0, l0); bsplit(x.y, h1, l1);
        bsplit(x.z, h2, l2); bsplit(x.w, h3, l3);
        __nv_bfloat162* ph = (__nv_bfloat162*)&sh[row * SROW + cs];
        ph[0] = __nv_bfloat162(h0, h1); ph[1] = __nv_bfloat162(h2, h3);
        __nv_bfloat162* pl = (__nv_bfloat162*)&sl[row * SROW + cs];
        pl[0] = __nv_bfloat162(l0, l1); pl[1] = __nv_bfloat162(l2, l3);
    }
}
// same but multiplies by wdot[k] while staging (for GEMM1's A)
__device__ __forceinline__ void stage_tile_w(const float* __restrict__ src, int ld, int k0,
                                             const float* __restrict__ wd,
                                             __nv_bfloat16* sh, __nv_bfloat16* sl, int t) {
    #pragma unroll
    for (int v = 0; v < 4; v++) {
        int idx = v * 256 + t;
        int row = idx >> 3;
        int cs  = (idx & 7) * 4;
        float4 x = *(const float4*)(src + (size_t)row * ld + k0 + cs);
        float4 w = *(const float4*)(wd + k0 + cs);
        x.x *= w.x; x.y *= w.y; x.z *= w.z; x.w *= w.w;
        __nv_bfloat16 h0, l0, h1, l1, h2, l2, h3, l3;
        bsplit(x.x, h0, l0); bsplit(x.y, h1, l1);
        bsplit(x.z, h2, l2); bsplit(x.w, h3, l3);
        __nv_bfloat162* ph = (__nv_bfloat162*)&sh[row * SROW + cs];
        ph[0] = __nv_bfloat162(h0, h1); ph[1] = __nv_bfloat162(h2, h3);
        __nv_bfloat162* pl = (__nv_bfloat162*)&sl[row * SROW + cs];
        pl[0] = __nv_bfloat162(l0, l1); pl[1] = __nv_bfloat162(l2, l3);
    }
}

// one k16 step: 4x4 m16n8 tiles, 3 precision passes
#define K16_STEP(kb)                                                          \
    do {                                                                      \
        uint32_t ah[4][4], al[4][4], bh[4][2], bl[4][2];                      \
        _Pragma("unroll")                                                     \
        for (int i = 0; i < 4; i++) {                                         \
            int r = wm * 64 + i * 16 + gr;                                    \
            const __nv_bfloat16* p = sAh + r * SROW + (kb) + 2 * qp;          \
            const __nv_bfloat16* q = sAl + r * SROW + (kb) + 2 * qp;          \
            ah[i][0] = L32(p);            ah[i][1] = L32(p + 8 * SROW);       \
            ah[i][2] = L32(p + 8);        ah[i][3] = L32(p + 8 * SROW + 8);   \
            al[i][0] = L32(q);            al[i][1] = L32(q + 8 * SROW);       \
            al[i][2] = L32(q + 8);        al[i][3] = L32(q + 8 * SROW + 8);   \
        }                                                                     \
        _Pragma("unroll")                                                     \
        for (int j = 0; j < 4; j++) {                                         \
            int c = wn * 32 + j * 8 + gr;                                     \
            const __nv_bfloat16* p = sBh + c * SROW + (kb) + 2 * qp;          \
            const __nv_bfloat16* q = sBl + c * SROW + (kb) + 2 * qp;          \
            bh[j][0] = L32(p); bh[j][1] = L32(p + 8);                         \
            bl[j][0] = L32(q); bl[j][1] = L32(q + 8);                         \
        }                                                                     \
        _Pragma("unroll")                                                     \
        for (int i = 0; i < 4; i++)                                           \
            _Pragma("unroll")                                                 \
            for (int j = 0; j < 4; j++) mma_bf16(acc[i][j], ah[i], bh[j]);    \
        _Pragma("unroll")                                                     \
        for (int i = 0; i < 4; i++)                                           \
            _Pragma("unroll")                                                 \
            for (int j = 0; j < 4; j++) mma_bf16(acc[i][j], ah[i], bl[j]);    \
        _Pragma("unroll")                                                     \
        for (int i = 0; i < 4; i++)                                           \
            _Pragma("unroll")                                                 \
            for (int j = 0; j < 4; j++) mma_bf16(acc[i][j], al[i], bh[j]);    \
    } while (0)

#define GEMM_PREAMBLE                                                         \
    __shared__ __nv_bfloat16 sAh[128 * SROW], sAl[128 * SROW];                \
    __shared__ __nv_bfloat16 sBh[128 * SROW], sBl[128 * SROW];                \
    int t = threadIdx.x;                                                      \
    int wid = t >> 5, lane = t & 31;                                          \
    int wm = wid >> 2, wn = wid & 3;                                          \
    int gr = lane >> 2, qp = lane & 3;                                        \
    float acc[4][4][4];                                                       \
    _Pragma("unroll")                                                         \
    for (int i = 0; i < 4; i++)                                               \
        _Pragma("unroll")                                                     \
        for (int j = 0; j < 4; j++)                                           \
            _Pragma("unroll")                                                 \
            for (int e = 0; e < 4; e++) acc[i][j][e] = 0.f;

// ---------------- transpose: dst[b,c,r] = src[b,r,c] -------------------------
__global__ void transpose_kernel(const float* __restrict__ src, int R, int C, int which) {
    __shared__ float tt[32][33];
    int b = blockIdx.z;
    int c0 = blockIdx.x * 32, r0 = blockIdx.y * 32;
    const float* s = src + (size_t)b * R * C;
    float* dst = ((which == 0) ? g_Udt : g_Uqt) + (size_t)b * R * C;
    for (int i = threadIdx.y; i < 32; i += 8)
        tt[i][threadIdx.x] = s[(size_t)(r0 + i) * C + c0 + threadIdx.x];
    __syncthreads();
    for (int i = threadIdx.y; i < 32; i += 8)
        dst[(size_t)(c0 + i) * R + r0 + threadIdx.x] = tt[threadIdx.x][i];
}

// ---------------- row dots ---------------------------------------------------
__global__ void rowdot_kernel(const float* __restrict__ X,
                              const float* __restrict__ w, int nrows, int mode) {
    int gw = (blockIdx.x * blockDim.x + threadIdx.x) >> 5;
    int lane = threadIdx.x & 31;
    if (gw >= nrows) return;
    const float* row = X + (size_t)gw * HH;
    float s = 0.f;
    #pragma unroll
    for (int k = lane * 4; k < HH; k += 128) {
        float4 v = *(const float4*)(row + k);
        float4 ww = *(const float4*)(w + k);
        s += v.x * ww.x + v.y * ww.y + v.z * ww.z + v.w * ww.w;
    }
    #pragma unroll
    for (int o = 16; o; o >>= 1) s += __shfl_xor_sync(0xffffffffu, s, o);
    if (lane == 0) { if (mode == 0) g_sd[gw] = s; else g_sq[gw] = s; }
}

// ---------------- GEMM1: S = (Ud*wdot) @ Uq^T + sd + sq + bias ---------------
// grid (DD/128, BB). A = Ud[b] (x wdot), B = Uq[b]. K = HH.
__global__ __launch_bounds__(256) void gemm1_mma(
    const float* __restrict__ Ud, const float* __restrict__ Uq,
    const float* __restrict__ wdot, const float* __restrict__ wcb) {
    GEMM_PREAMBLE
    int b = blockIdx.y, m0 = blockIdx.x * 128;
    const float* A = Ud + (size_t)b * DD * HH + (size_t)m0 * HH;
    const float* B = Uq + (size_t)b * QQ * HH;

    for (int k0 = 0; k0 < HH; k0 += 32) {
        __syncthreads();
        stage_tile_w(A, HH, k0, wdot, sAh, sAl, t);
        stage_tile  (B, HH, k0, sBh, sBl, t);
        __syncthreads();
        K16_STEP(0);
        K16_STEP(16);
    }

    float bias = wcb[0];
    #pragma unroll
    for (int i = 0; i < 4; i++) {
        int m = m0 + wm * 64 + i * 16 + gr;
        float sd0 = g_sd[b * DD + m] + bias;
        float sd1 = g_sd[b * DD + m + 8] + bias;
        #pragma unroll
        for (int j = 0; j < 4; j++) {
            int n = wn * 32 + j * 8 + 2 * qp;
            float sq0 = g_sq[b * QQ + n], sq1 = g_sq[b * QQ + n + 1];
            float* d0 = g_S + ((size_t)b * DD + m) * QQ + n;
            float* d1 = g_S + ((size_t)b * DD + m + 8) * QQ + n;
            *(float2*)d0 = make_float2(acc[i][j][0] + sd0 + sq0, acc[i][j][1] + sd0 + sq1);
            *(float2*)d1 = make_float2(acc[i][j][2] + sd1 + sq0, acc[i][j][3] + sd1 + sq1);
        }
    }
}

// ---------------- GEMM3: Tt[h,q] = sum_d Udt[h,d] * P2t[q,d] -----------------
// grid (HH/128, BB). A = Udt[b], B = P2t[b]. K = DD.
__global__ __launch_bounds__(256) void gemm3_mma() {
    GEMM_PREAMBLE
    int b = blockIdx.y, m0 = blockIdx.x * 128;
    const float* A = g_Udt + (size_t)b * HH * DD + (size_t)m0 * DD;
    const float* B = g_P2t + (size_t)b * QQ * DD;

    for (int k0 = 0; k0 < DD; k0 += 32) {
        __syncthreads();
        stage_tile(A, DD, k0, sAh, sAl, t);
        stage_tile(B, DD, k0, sBh, sBl, t);
        __syncthreads();
        K16_STEP(0);
        K16_STEP(16);
    }

    #pragma unroll
    for (int i = 0; i < 4; i++) {
        int m = m0 + wm * 64 + i * 16 + gr;
        #pragma unroll
        for (int j = 0; j < 4; j++) {
            int n = wn * 32 + j * 8 + 2 * qp;
            float* d0 = g_Tt + ((size_t)b * HH + m) * QQ + n;
            float* d1 = g_Tt + ((size_t)b * HH + m + 8) * QQ + n;
            *(float2*)d0 = make_float2(acc[i][j][0], acc[i][j][1]);
            *(float2*)d1 = make_float2(acc[i][j][2], acc[i][j][3]);
        }
    }
}

// ---------------- GEMM2/4: C[d,h] = sum_q P1[d,q] * Bt[h,q] ------------------
// grid (HH/128, DD/128, BB). mode 0: Bt = Uqt, writes slices 0,1,2.
//                            mode 1: Bt = Tt,  writes slice 3.
__global__ __launch_bounds__(256) void gemm24_mma(
    const float* __restrict__ Ud, float* __restrict__ out, int mode) {
    GEMM_PREAMBLE
    int b = blockIdx.z, n0 = blockIdx.x * 128, m0 = blockIdx.y * 128;
    const float* A = g_P1 + (size_t)b * DD * QQ + (size_t)m0 * QQ;
    const float* B = ((mode == 0) ? g_Uqt : g_Tt) + (size_t)b * HH * QQ + (size_t)n0 * QQ;

    for (int k0 = 0; k0 < QQ; k0 += 32) {
        __syncthreads();
        stage_tile(A, QQ, k0, sAh, sAl, t);
        stage_tile(B, QQ, k0, sBh, sBl, t);
        __syncthreads();
        K16_STEP(0);
        K16_STEP(16);
    }

    #pragma unroll
    for (int i = 0; i < 4; i++) {
        int m = m0 + wm * 64 + i * 16 + gr;
        #pragma unroll
        for (int j = 0; j < 4; j++) {
            int n = n0 + wn * 32 + j * 8 + 2 * qp;
            #pragma unroll
            for (int rr = 0; rr < 2; rr++) {
                int mm = m + rr * 8;
                float a0 = acc[i][j][2 * rr], a1 = acc[i][j][2 * rr + 1];
                float2 u = *(const float2*)(Ud + ((size_t)b * DD + mm) * HH + n);
                float* ob = out + ((size_t)b * DD + mm) * (size_t)(4 * HH) + n;
                if (mode == 0) {
                    *(float2*)(ob)          = u;
                    *(float2*)(ob + HH)     = make_float2(a0, a1);
                    *(float2*)(ob + 2 * HH) = make_float2(u.x * a0, u.y * a1);
                } else {
                    *(float2*)(ob + 3 * HH) = make_float2(u.x * a0, u.y * a1);
                }
            }
        }
    }
}

// ---------------- softmax over q (axis -1): g_S -> g_P1 ----------------------
__global__ void softmax_d2q_kernel(const int* __restrict__ qm,
                                   const int* __restrict__ dmk) {
    int row = (blockIdx.x * blockDim.x + threadIdx.x) >> 5;
    if (row >= BB * DD) return;
    int lane = threadIdx.x & 31;
    int b = row >> 10;
    int dmv = dmk[row];
    const float* src = g_S + (size_t)row * QQ;
    float4 v = *(const float4*)(src + lane * 4);
    int4 q4 = *(const int4*)(qm + b * QQ + lane * 4);
    int mk0 = (dmv > 0) && (q4.x > 0), mk1 = (dmv > 0) && (q4.y > 0);
    int mk2 = (dmv > 0) && (q4.z > 0), mk3 = (dmv > 0) && (q4.w > 0);
    float l0 = mk0 ? v.x : -1e30f, l1 = mk1 ? v.y : -1e30f;
    float l2 = mk2 ? v.z : -1e30f, l3 = mk3 ? v.w : -1e30f;
    float mx = fmaxf(fmaxf(l0, l1), fmaxf(l2, l3));
    #pragma unroll
    for (int o = 16; o; o >>= 1) mx = fmaxf(mx, __shfl_xor_sync(0xffffffffu, mx, o));
    float e0 = __expf(l0 - mx), e1 = __expf(l1 - mx);
    float e2 = __expf(l2 - mx), e3 = __expf(l3 - mx);
    float s = e0 + e1 + e2 + e3;
    #pragma unroll
    for (int o = 16; o; o >>= 1) s += __shfl_xor_sync(0xffffffffu, s, o);
    float inv = 1.f / s;
    float4 ov;
    ov.x = mk0 ? e0 * inv : 0.f; ov.y = mk1 ? e1 * inv : 0.f;
    ov.z = mk2 ? e2 * inv : 0.f; ov.w = mk3 ? e3 * inv : 0.f;
    *(float4*)(g_P1 + (size_t)row * QQ + lane * 4) = ov;
}

// ---------------- softmax over d (axis -2): g_S -> g_P2t (transposed) --------
__global__ void softmax_q2d_kernel(const int* __restrict__ qm,
                                   const int* __restrict__ dmk) {
    __shared__ float sm[8][32], ss[8][32], sM[32], sI[32];
    __shared__ float tile[32][33];
    int b = blockIdx.y;
    int tx = threadIdx.x, ty = threadIdx.y;
    int q = blockIdx.x * 32 + tx;
    int qmv = qm[b * QQ + q];
    const float* base = g_S + (size_t)b * DD * QQ + q;
    float m = -1e30f, s = 0.f;
    for (int d = ty; d < DD; d += 8) {
        int mk = (qmv > 0) && (dmk[b * DD + d] > 0);
        float v = mk ? base[(size_t)d * QQ] : -1e30f;
        float nm = fmaxf(m, v);
        s = s * __expf(m - nm) + __expf(v - nm);
        m = nm;
    }
    sm[ty][tx] = m; ss[ty][tx] = s;
    __syncthreads();
    if (ty == 0) {
        float M = -1e30f;
        #pragma unroll
        for (int j = 0; j < 8; j++) M = fmaxf(M, sm[j][tx]);
        float S = 0.f;
        #pragma unroll
        for (int j = 0; j < 8; j++) S += ss[j][tx] * __expf(sm[j][tx] - M);
        sM[tx] = M; sI[tx] = 1.f / S;
    }
    __syncthreads();
    float M = sM[tx], inv = sI[tx];
    int tid = ty * 32 + tx;
    int qr = tid >> 3, seg = (tid & 7) * 4;
    float* drow = g_P2t + (size_t)b * QQ * DD + (size_t)(blockIdx.x * 32 + qr) * DD;
    for (int d0 = 0; d0 < DD; d0 += 32) {
        #pragma unroll
        for (int dj = ty; dj < 32; dj += 8) {
            int d = d0 + dj;
            int mk = (qmv > 0) && (dmk[b * DD + d] > 0);
            float v = base[(size_t)d * QQ];
            tile[tx][dj] = mk ? __expf(v - M) * inv : 0.f;
        }
        __syncthreads();
        float4 o = make_float4(tile[qr][seg], tile[qr][seg + 1],
                               tile[qr][seg + 2], tile[qr][seg + 3]);
        *(float4*)(drow + d0 + seg) = o;
        __syncthreads();
    }
}

// ---------------------------------------------------------------------------
extern "C" void kernel_launch(void* const* d_in, const int* in_sizes, int n_in,
                              void* d_out, int out_size) {
    const float* Ud  = (const float*)d_in[0];
    const float* Uq  = (const float*)d_in[1];
    const float* wcw = (const float*)d_in[2];
    const float* wcb = (const float*)d_in[3];
    const int*   qm  = (const int*)d_in[4];
    const int*   dmk = (const int*)d_in[5];
    float* out = (float*)d_out;

    // transposes for K-major operands
    transpose_kernel<<<dim3(HH / 32, DD / 32, BB), dim3(32, 8)>>>(Ud, DD, HH, 0);
    transpose_kernel<<<dim3(HH / 32, QQ / 32, BB), dim3(32, 8)>>>(Uq, QQ, HH, 1);

    // s_d, s_q
    rowdot_kernel<<<(BB * DD) / 8, 256>>>(Ud, wcw, BB * DD, 0);
    rowdot_kernel<<<(BB * QQ) / 8, 256>>>(Uq, wcw + HH, BB * QQ, 1);

    // logits
    gemm1_mma<<<dim3(DD / 128, BB), 256>>>(Ud, Uq, wcw + 2 * HH, wcb);

    // softmaxes
    softmax_d2q_kernel<<<(BB * DD) / 8, 256>>>(qm, dmk);
    softmax_q2d_kernel<<<dim3(QQ / 32, BB), dim3(32, 8)>>>(qm, dmk);

    // Tt = (P2^T @ Ud)^T
    gemm3_mma<<<dim3(HH / 128, BB), 256>>>();

    // A_d2q (slices 0,1,2) and A_q2d (slice 3)
    gemm24_mma<<<dim3(HH / 128, DD / 128, BB), 256>>>(Ud, out, 0);
    gemm24_mma<<<dim3(HH / 128, DD / 128, BB), 256>>>(Ud, out, 1);
}